// round 15
// baseline (speedup 1.0000x reference)
#include <cuda_runtime.h>

#define NPTS 262144
#define NSAMP 8
#define NPAIR (NPTS * NSAMP)
#define QTR_N (NPTS / 4)
#define EPSBN 1e-5f
#define FULLM 0xffffffffu
#define QKVB 2048          // qkv blocks (grid-stride over 4096 chunks)
#define PSTB 1024          // pstats blocks
#define G_PERS 608         // 4 blocks/SM * 152 SMs (GB300) — all resident

typedef unsigned long long ull;

// ---------------- static device scratch (zero-initialized at module load) --------
__device__ float g_q[NPTS * 32];
__device__ float g_k[NPTS * 32];
__device__ float g_v[NPTS * 32];
__device__ float g_t3[NPAIR * 3];   // relu(bn_p(p_r @ Wp1.T + bp1)) per pair (24 MB)
__device__ float g_t[NPAIR * 4];    // t pre-BN (32 MB)
// [0..2] psum [3..5] psq  [6..37] wsum [38..69] wsq  [70..73] tsum [74..77] tsq
__device__ double g_acc[78];
__device__ unsigned int g_ctr;
__device__ unsigned int g_bar[2];   // grid barriers (reset by final ticket)

// ---------------- f32x2 packed-FMA helpers ----------------
__device__ __forceinline__ void ffma2(ull &acc, ull a, ull b) {
    asm("fma.rn.f32x2 %0, %1, %2, %0;" : "+l"(acc) : "l"(a), "l"(b));
}
__device__ __forceinline__ ull pack2(float x) {
    ull r;
    asm("mov.b64 %0, {%1, %1};" : "=l"(r) : "f"(x));
    return r;
}
__device__ __forceinline__ ull pack2b(float lo, float hi) {
    ull r;
    asm("mov.b64 %0, {%1, %2};" : "=l"(r) : "f"(lo), "f"(hi));
    return r;
}
__device__ __forceinline__ void unpack2(ull v, float &lo, float &hi) {
    asm("mov.b64 {%0, %1}, %2;" : "=f"(lo), "=f"(hi) : "l"(v));
}

// ---------------- grid-wide software barrier (all blocks resident) ---------------
__device__ __forceinline__ void grid_sync(unsigned int* bar) {
    __syncthreads();
    if (threadIdx.x == 0) {
        __threadfence();
        atomicAdd(bar, 1u);
        while (*(volatile unsigned int*)bar < (unsigned int)gridDim.x) { }
    }
    __syncthreads();
}

// ---------------- K1: fused qkv (blocks 0..QKVB-1, f32x2) + pstats ---------------
__global__ void __launch_bounds__(256) k_fused1(
        const float* __restrict__ p, const float* __restrict__ x,
        const int* __restrict__ idx,
        const float* __restrict__ Wq, const float* __restrict__ bq,
        const float* __restrict__ Wk, const float* __restrict__ bk,
        const float* __restrict__ Wv, const float* __restrict__ bv,
        const float* __restrict__ Wp1, const float* __restrict__ bp1) {
    int tid = threadIdx.x;
    if (blockIdx.x < QKVB) {
        __shared__ ull sW2[3][1024];
        __shared__ ull sx2[8][4][32];
        __shared__ float sb[3][32];
        for (int e = tid; e < 1024; e += 256) {
            int c = e >> 5, i = e & 31;
            sW2[0][i * 32 + c] = pack2(Wq[e]);
            sW2[1][i * 32 + c] = pack2(Wk[e]);
            sW2[2][i * 32 + c] = pack2(Wv[e]);
        }
        if (tid < 32) { sb[0][tid] = bq[tid]; sb[1][tid] = bk[tid]; sb[2][tid] = bv[tid]; }
        __syncthreads();
        int wid = tid >> 5, lane = tid & 31;
        ull bias2[3] = { pack2(sb[0][lane]), pack2(sb[1][lane]), pack2(sb[2][lane]) };
        float* sxf = (float*)&sx2[wid][0][0];
        for (int chunk = blockIdx.x; chunk < NPTS / 64; chunk += QKVB) {
            int n0 = chunk * 64 + wid * 8;
#pragma unroll
            for (int pp = 0; pp < 8; pp++) {
                float v = x[(n0 + pp) * 32 + lane];
                sxf[((pp >> 1) * 32 + lane) * 2 + (pp & 1)] = v;
            }
            __syncwarp();
            ull acc[3][4];
#pragma unroll
            for (int m = 0; m < 3; m++)
#pragma unroll
                for (int pr = 0; pr < 4; pr++) acc[m][pr] = bias2[m];
#pragma unroll 4
            for (int i = 0; i < 32; i++) {
                ull w0 = sW2[0][i * 32 + lane];
                ull w1 = sW2[1][i * 32 + lane];
                ull w2 = sW2[2][i * 32 + lane];
#pragma unroll
                for (int pr = 0; pr < 4; pr++) {
                    ull xp = sx2[wid][pr][i];
                    ffma2(acc[0][pr], w0, xp);
                    ffma2(acc[1][pr], w1, xp);
                    ffma2(acc[2][pr], w2, xp);
                }
            }
#pragma unroll
            for (int pr = 0; pr < 4; pr++) {
                float lo, hi;
                unpack2(acc[0][pr], lo, hi);
                g_q[(n0 + 2 * pr) * 32 + lane] = lo;
                g_q[(n0 + 2 * pr + 1) * 32 + lane] = hi;
                unpack2(acc[1][pr], lo, hi);
                g_k[(n0 + 2 * pr) * 32 + lane] = lo;
                g_k[(n0 + 2 * pr + 1) * 32 + lane] = hi;
                unpack2(acc[2][pr], lo, hi);
                g_v[(n0 + 2 * pr) * 32 + lane] = lo;
                g_v[(n0 + 2 * pr + 1) * 32 + lane] = hi;
            }
            __syncwarp();
        }
    } else {
        float W[9], b3[3];
#pragma unroll
        for (int i = 0; i < 9; i++) W[i] = Wp1[i];
#pragma unroll
        for (int i = 0; i < 3; i++) b3[i] = bp1[i];
        float s0 = 0, s1 = 0, s2 = 0, q0 = 0, q1 = 0, q2 = 0;
        int bid = blockIdx.x - QKVB;
        for (int pr = bid * 256 + tid; pr < NPAIR; pr += PSTB * 256) {
            int n = pr >> 3;
            int j = __ldg(&idx[pr]);
            float d0 = __ldg(&p[j * 3 + 0]) - __ldg(&p[n * 3 + 0]);
            float d1 = __ldg(&p[j * 3 + 1]) - __ldg(&p[n * 3 + 1]);
            float d2 = __ldg(&p[j * 3 + 2]) - __ldg(&p[n * 3 + 2]);
            float y0 = W[0] * d0 + W[1] * d1 + W[2] * d2 + b3[0];
            float y1 = W[3] * d0 + W[4] * d1 + W[5] * d2 + b3[1];
            float y2 = W[6] * d0 + W[7] * d1 + W[8] * d2 + b3[2];
            s0 += y0; q0 += y0 * y0;
            s1 += y1; q1 += y1 * y1;
            s2 += y2; q2 += y2 * y2;
        }
#pragma unroll
        for (int o = 16; o; o >>= 1) {
            s0 += __shfl_xor_sync(FULLM, s0, o);
            s1 += __shfl_xor_sync(FULLM, s1, o);
            s2 += __shfl_xor_sync(FULLM, s2, o);
            q0 += __shfl_xor_sync(FULLM, q0, o);
            q1 += __shfl_xor_sync(FULLM, q1, o);
            q2 += __shfl_xor_sync(FULLM, q2, o);
        }
        __shared__ double sh6[6];
        if (tid < 6) sh6[tid] = 0.0;
        __syncthreads();
        if ((tid & 31) == 0) {
            atomicAdd(&sh6[0], (double)s0);
            atomicAdd(&sh6[1], (double)s1);
            atomicAdd(&sh6[2], (double)s2);
            atomicAdd(&sh6[3], (double)q0);
            atomicAdd(&sh6[4], (double)q1);
            atomicAdd(&sh6[5], (double)q2);
        }
        __syncthreads();
        if (tid < 6) atomicAdd(&g_acc[tid], sh6[tid]);
    }
}

// ---------------- K2: persistent gather kernel — 3 phases + 2 grid barriers ------
__global__ void __launch_bounds__(256, 4) k_gather(
        const float* __restrict__ p, const int* __restrict__ idx,
        const float* __restrict__ gp, const float* __restrict__ bpv,
        const float* __restrict__ Wp1, const float* __restrict__ bp1,
        const float* __restrict__ Wp2, const float* __restrict__ bp2,
        const float* __restrict__ gw1, const float* __restrict__ bw1,
        const float* __restrict__ Ww1, const float* __restrict__ bww1,
        const float* __restrict__ gw2, const float* __restrict__ bw2,
        const float* __restrict__ Ww2, const float* __restrict__ bww2,
        float* __restrict__ out) {
    __shared__ float s_c0[3], s_c1[3];              // bn_p coefs
    __shared__ double shs[32], shq[32];
    __shared__ float s_a32[32], s_c32[32];          // bn_w coefs
    __shared__ __align__(16) float sw[8][4][8][36];
    __shared__ __align__(16) float st3[8][4][8][4]; // t3 broadcast staging (4 KB)
    __shared__ __align__(16) float sWw1[4 * 36];
    __shared__ double sh8[8];
    __shared__ float s_a4[4], s_c4[4];              // bn_t coefs
    int tid = threadIdx.x, lane = tid & 31, wid = tid >> 5;
    int gw = blockIdx.x * 8 + wid, nw = gridDim.x * 8;
    int m4 = lane & 3, pl = lane >> 2;
    int pr_i = (lane < 24) ? lane : 23;
    int pair = pr_i / 3, comp = pr_i - pair * 3;
    float w20 = Wp2[lane * 3 + 0], w21 = Wp2[lane * 3 + 1], w22 = Wp2[lane * 3 + 2];
    float b2 = bp2[lane];

    // ================= phase 1: t3-gen + wstats =================
    {
        if (tid < 3) {
            double M = (double)NPAIR;
            double m = g_acc[tid] / M;
            double var = g_acc[3 + tid] / M - m * m;
            float a = gp[tid] * rsqrtf((float)var + EPSBN);
            s_c0[tid] = a; s_c1[tid] = bpv[tid] - (float)m * a;
        }
        if (tid < 32) { shs[tid] = 0.0; shq[tid] = 0.0; }
        __syncthreads();
        float wc0 = Wp1[comp * 3 + 0], wc1 = Wp1[comp * 3 + 1], wc2 = Wp1[comp * 3 + 2];
        float b3c = bp1[comp];
        float apc = s_c0[comp], cpc = s_c1[comp];
        float s = 0.f, ss = 0.f;
        for (int n = gw; n < QTR_N; n += nw) {
            int jv[4];
            float base[4], t3r[4];
#pragma unroll
            for (int s4 = 0; s4 < 4; s4++) {
                int nn = n + s4 * QTR_N;
                jv[s4] = (lane < 8) ? __ldg(&idx[nn * 8 + lane]) : 0;
                base[s4] = b2 - __ldg(&g_q[nn * 32 + lane]);
            }
            float pd[4];
#pragma unroll
            for (int s4 = 0; s4 < 4; s4++) {
                int nn = n + s4 * QTR_N;
                int jm = __shfl_sync(FULLM, jv[s4], pair);
                pd[s4] = __ldg(&p[jm * 3 + comp]) - __ldg(&p[nn * 3 + comp]);
            }
#pragma unroll
            for (int s4 = 0; s4 < 4; s4++) {
                float d0 = __shfl_sync(FULLM, pd[s4], pair * 3 + 0);
                float d1 = __shfl_sync(FULLM, pd[s4], pair * 3 + 1);
                float d2 = __shfl_sync(FULLM, pd[s4], pair * 3 + 2);
                float y = wc0 * d0 + wc1 * d1 + wc2 * d2 + b3c;
                t3r[s4] = fmaxf(0.f, apc * y + cpc);
            }
            if (lane < 24) {
#pragma unroll
                for (int s4 = 0; s4 < 4; s4++)
                    st3[wid][s4][pair][comp] = t3r[s4];
            }
            __syncwarp();
#pragma unroll
            for (int ns = 0; ns < 8; ns++)
#pragma unroll
                for (int s4 = 0; s4 < 4; s4++) {
                    int j = __shfl_sync(FULLM, jv[s4], ns);
                    float kv = __ldg(&g_k[j * 32 + lane]);
                    float4 t = *(const float4*)&st3[wid][s4][ns][0];
                    float prc = w20 * t.x + w21 * t.y + w22 * t.z + base[s4];
                    float wv = kv + prc;
                    s += wv; ss += wv * wv;
                }
            if (lane < 24) {
#pragma unroll
                for (int s4 = 0; s4 < 4; s4++)
                    g_t3[(n + s4 * QTR_N) * 24 + lane] = t3r[s4];
            }
            __syncwarp();
        }
        atomicAdd(&shs[lane], (double)s);
        atomicAdd(&shq[lane], (double)ss);
        __syncthreads();
        if (tid < 32) {
            atomicAdd(&g_acc[6 + tid], shs[tid]);
            atomicAdd(&g_acc[38 + tid], shq[tid]);
        }
    }
    grid_sync(&g_bar[0]);

    // ================= phase 2: t = relu(bn_w(w)) @ Ww1.T + bww1 =================
    {
        if (tid < 32) {
            double M = (double)NPAIR;
            double m = g_acc[6 + tid] / M;
            double var = g_acc[38 + tid] / M - m * m;
            float a = gw1[tid] * rsqrtf((float)var + EPSBN);
            s_a32[tid] = a; s_c32[tid] = bw1[tid] - (float)m * a;
        }
        if (tid < 128) sWw1[(tid >> 5) * 36 + (tid & 31)] = Ww1[tid];
        if (tid < 8) sh8[tid] = 0.0;
        __syncthreads();
        float aw = s_a32[lane], cw = s_c32[lane];
        float bm = bww1[m4];
        const ulonglong2* wr2 = (const ulonglong2*)&sWw1[m4 * 36];
        float sm = 0.f, qm = 0.f;
        for (int n = gw; n < QTR_N; n += nw) {
            int jv[4];
            float base[4];
#pragma unroll
            for (int s4 = 0; s4 < 4; s4++) {
                int nn = n + s4 * QTR_N;
                jv[s4] = (lane < 8) ? __ldg(&idx[nn * 8 + lane]) : 0;
                base[s4] = b2 - __ldg(&g_q[nn * 32 + lane]);
                if (lane < 24)
                    st3[wid][s4][pair][comp] = __ldg(&g_t3[nn * 24 + lane]);
            }
            __syncwarp();
#pragma unroll
            for (int ns = 0; ns < 8; ns++)
#pragma unroll
                for (int s4 = 0; s4 < 4; s4++) {
                    int j = __shfl_sync(FULLM, jv[s4], ns);
                    float kv = __ldg(&g_k[j * 32 + lane]);
                    float4 t = *(const float4*)&st3[wid][s4][ns][0];
                    float prc = w20 * t.x + w21 * t.y + w22 * t.z + base[s4];
                    float wv = kv + prc;
                    sw[wid][s4][ns][lane] = fmaxf(0.f, aw * wv + cw);
                }
            __syncwarp();
            // 32-wide dot in packed f32x2: 64 FFMA2 instead of 128 FMA
            ull tv2[4];
#pragma unroll
            for (int s4 = 0; s4 < 4; s4++) tv2[s4] = pack2b(bm, 0.f);
#pragma unroll
            for (int c4 = 0; c4 < 8; c4++) {
                ulonglong2 bv = wr2[c4];
#pragma unroll
                for (int s4 = 0; s4 < 4; s4++) {
                    ulonglong2 av = *(const ulonglong2*)&sw[wid][s4][pl][c4 * 4];
                    ffma2(tv2[s4], av.x, bv.x);
                    ffma2(tv2[s4], av.y, bv.y);
                }
            }
#pragma unroll
            for (int s4 = 0; s4 < 4; s4++) {
                float lo, hi;
                unpack2(tv2[s4], lo, hi);
                float tv = lo + hi;
                g_t[(n + s4 * QTR_N) * 32 + lane] = tv;
                sm += tv; qm += tv * tv;
            }
            __syncwarp();
        }
#pragma unroll
        for (int o = 4; o < 32; o <<= 1) {
            sm += __shfl_xor_sync(FULLM, sm, o);
            qm += __shfl_xor_sync(FULLM, qm, o);
        }
        if (lane < 4) {
            atomicAdd(&sh8[lane], (double)sm);
            atomicAdd(&sh8[4 + lane], (double)qm);
        }
        __syncthreads();
        if (tid < 8) atomicAdd(&g_acc[70 + tid], sh8[tid]);
    }
    grid_sync(&g_bar[1]);

    // ================= phase 3: softmax + weighted sum -> out =================
    {
        if (tid < 4) {
            double M = (double)NPAIR;
            double m = g_acc[70 + tid] / M;
            double var = g_acc[74 + tid] / M - m * m;
            float a = gw2[tid] * rsqrtf((float)var + EPSBN);
            s_a4[tid] = a; s_c4[tid] = bw2[tid] - (float)m * a;
        }
        __syncthreads();
        float at0 = s_a4[0], at1 = s_a4[1], at2 = s_a4[2], at3 = s_a4[3];
        float ct0 = s_c4[0], ct1 = s_c4[1], ct2 = s_c4[2], ct3 = s_c4[3];
        float v20 = Ww2[m4 * 4 + 0], v21 = Ww2[m4 * 4 + 1];
        float v22 = Ww2[m4 * 4 + 2], v23 = Ww2[m4 * 4 + 3];
        float bcc = bww2[m4];
        for (int n = gw; n < QTR_N; n += nw) {
            int jv[4];
            float l[4];
#pragma unroll
            for (int s4 = 0; s4 < 4; s4++) {
                int nn = n + s4 * QTR_N;
                jv[s4] = (lane < 8) ? __ldg(&idx[nn * 8 + lane]) : 0;
                if (lane < 24)
                    st3[wid][s4][pair][comp] = __ldg(&g_t3[nn * 24 + lane]);
                float4 t4 = __ldg((const float4*)&g_t[nn * 32 + pl * 4]);
                float u0 = fmaxf(0.f, at0 * t4.x + ct0);
                float u1 = fmaxf(0.f, at1 * t4.y + ct1);
                float u2 = fmaxf(0.f, at2 * t4.z + ct2);
                float u3 = fmaxf(0.f, at3 * t4.w + ct3);
                l[s4] = v20 * u0 + v21 * u1 + v22 * u2 + v23 * u3 + bcc;
            }
            __syncwarp();
            float mx[4];
#pragma unroll
            for (int s4 = 0; s4 < 4; s4++) mx[s4] = l[s4];
#pragma unroll
            for (int o = 4; o < 32; o <<= 1)
#pragma unroll
                for (int s4 = 0; s4 < 4; s4++)
                    mx[s4] = fmaxf(mx[s4], __shfl_xor_sync(FULLM, mx[s4], o));
            float wn[4], sum[4];
#pragma unroll
            for (int s4 = 0; s4 < 4; s4++) { wn[s4] = __expf(l[s4] - mx[s4]); sum[s4] = wn[s4]; }
#pragma unroll
            for (int o = 4; o < 32; o <<= 1)
#pragma unroll
                for (int s4 = 0; s4 < 4; s4++)
                    sum[s4] += __shfl_xor_sync(FULLM, sum[s4], o);
#pragma unroll
            for (int s4 = 0; s4 < 4; s4++) wn[s4] /= sum[s4];
            float T0[4], T1[4], T2[4];
#pragma unroll
            for (int s4 = 0; s4 < 4; s4++) {
                float4 tm = *(const float4*)&st3[wid][s4][pl][0];
                T0[s4] = wn[s4] * tm.x;
                T1[s4] = wn[s4] * tm.y;
                T2[s4] = wn[s4] * tm.z;
            }
#pragma unroll
            for (int o = 4; o < 32; o <<= 1)
#pragma unroll
                for (int s4 = 0; s4 < 4; s4++) {
                    T0[s4] += __shfl_xor_sync(FULLM, T0[s4], o);
                    T1[s4] += __shfl_xor_sync(FULLM, T1[s4], o);
                    T2[s4] += __shfl_xor_sync(FULLM, T2[s4], o);
                }
            float o4[4] = {0.f, 0.f, 0.f, 0.f};
#pragma unroll
            for (int ns = 0; ns < 8; ns++)
#pragma unroll
                for (int s4 = 0; s4 < 4; s4++) {
                    int j = __shfl_sync(FULLM, jv[s4], ns);
                    float wg = __shfl_sync(FULLM, wn[s4], ns * 4 + m4);
                    o4[s4] += __ldg(&g_v[j * 32 + lane]) * wg;
                }
#pragma unroll
            for (int s4 = 0; s4 < 4; s4++)
                out[(n + s4 * QTR_N) * 32 + lane] =
                    o4[s4] + w20 * T0[s4] + w21 * T1[s4] + w22 * T2[s4] + b2;
            __syncwarp();
        }
    }
    // last-finishing block resets accumulators + barriers for the next replay
    __syncthreads();
    if (tid == 0) {
        __threadfence();
        unsigned int tk = atomicAdd(&g_ctr, 1u);
        if (tk == gridDim.x - 1) {
            for (int i = 0; i < 78; i++) g_acc[i] = 0.0;
            g_bar[0] = 0u; g_bar[1] = 0u;
            g_ctr = 0u;
        }
    }
}

// ---------------- launch ----------------
extern "C" void kernel_launch(void* const* d_in, const int* in_sizes, int n_in,
                              void* d_out, int out_size) {
    const float* p   = (const float*)d_in[0];
    const float* x   = (const float*)d_in[1];
    const int*   idx = (const int*)d_in[2];
    const float* Wq  = (const float*)d_in[3];  const float* bq   = (const float*)d_in[4];
    const float* Wk  = (const float*)d_in[5];  const float* bk   = (const float*)d_in[6];
    const float* Wv  = (const float*)d_in[7];  const float* bv   = (const float*)d_in[8];
    const float* Wp1 = (const float*)d_in[9];  const float* bp1  = (const float*)d_in[10];
    const float* gp  = (const float*)d_in[11]; const float* bp   = (const float*)d_in[12];
    const float* Wp2 = (const float*)d_in[13]; const float* bp2  = (const float*)d_in[14];
    const float* gw1 = (const float*)d_in[15]; const float* bw1  = (const float*)d_in[16];
    const float* Ww1 = (const float*)d_in[17]; const float* bww1 = (const float*)d_in[18];
    const float* gw2 = (const float*)d_in[19]; const float* bw2  = (const float*)d_in[20];
    const float* Ww2 = (const float*)d_in[21]; const float* bww2 = (const float*)d_in[22];
    float* out = (float*)d_out;

    k_fused1<<<QKVB + PSTB, 256>>>(p, x, idx, Wq, bq, Wk, bk, Wv, bv, Wp1, bp1);
    k_gather<<<G_PERS, 256>>>(p, idx, gp, bp, Wp1, bp1, Wp2, bp2,
                              gw1, bw1, Ww1, bww1, gw2, bw2, Ww2, bww2, out);
}

// round 16
// speedup vs baseline: 1.0625x; 1.0625x over previous
#include <cuda_runtime.h>

#define NPTS 262144
#define NSAMP 8
#define NPAIR (NPTS * NSAMP)
#define QTR_N (NPTS / 4)
#define EPSBN 1e-5f
#define FULLM 0xffffffffu
#define G_PERS 608         // 4 blocks/SM * 152 SMs (GB300) — all resident
#define NCHUNK (NPTS / 64) // 4096 qkv chunks

typedef unsigned long long ull;

// ---------------- static device scratch (zero-initialized at module load) --------
__device__ float g_q[NPTS * 32];
__device__ float g_k[NPTS * 32];
__device__ float g_v[NPTS * 32];
__device__ float g_t3[NPAIR * 3];   // relu(bn_p(p_r @ Wp1.T + bp1)) per pair (24 MB)
__device__ float g_t[NPAIR * 4];    // t pre-BN (32 MB)
// [0..2] psum [3..5] psq  [6..37] wsum [38..69] wsq  [70..73] tsum [74..77] tsq
__device__ double g_acc[78];
__device__ unsigned int g_ctr;
__device__ unsigned int g_bar[3];   // grid barriers (reset by final ticket)

// ---------------- f32x2 packed-FMA helpers ----------------
__device__ __forceinline__ void ffma2(ull &acc, ull a, ull b) {
    asm("fma.rn.f32x2 %0, %1, %2, %0;" : "+l"(acc) : "l"(a), "l"(b));
}
__device__ __forceinline__ ull pack2(float x) {
    ull r;
    asm("mov.b64 %0, {%1, %1};" : "=l"(r) : "f"(x));
    return r;
}
__device__ __forceinline__ void unpack2(ull v, float &lo, float &hi) {
    asm("mov.b64 {%0, %1}, %2;" : "=f"(lo), "=f"(hi) : "l"(v));
}

// ---------------- grid-wide software barrier (all blocks resident) ---------------
__device__ __forceinline__ void grid_sync(unsigned int* bar) {
    __threadfence();
    __syncthreads();
    if (threadIdx.x == 0) {
        atomicAdd(bar, 1u);
        while (*(volatile unsigned int*)bar < (unsigned int)gridDim.x) { }
    }
    __syncthreads();
}

// ---------------- one persistent kernel: 4 phases, 3 grid barriers ---------------
__global__ void __launch_bounds__(256, 4) k_all(
        const float* __restrict__ p, const float* __restrict__ x,
        const int* __restrict__ idx,
        const float* __restrict__ Wq, const float* __restrict__ bq,
        const float* __restrict__ Wk, const float* __restrict__ bk,
        const float* __restrict__ Wv, const float* __restrict__ bv,
        const float* __restrict__ gp, const float* __restrict__ bpv,
        const float* __restrict__ Wp1, const float* __restrict__ bp1,
        const float* __restrict__ Wp2, const float* __restrict__ bp2,
        const float* __restrict__ gw1, const float* __restrict__ bw1,
        const float* __restrict__ Ww1, const float* __restrict__ bww1,
        const float* __restrict__ gw2, const float* __restrict__ bw2,
        const float* __restrict__ Ww2, const float* __restrict__ bww2,
        float* __restrict__ out) {
    // phase-disjoint shared memory: qkv overlay vs gather overlay
    __shared__ __align__(16) union {
        struct { ull sW2[3][1024]; ull sx2[8][4][32]; float sb[3][32]; } q;   // ~33 KB
        struct { float sw[8][4][8][36]; float st3[8][4][8][4]; float sWw1[144]; } g; // ~41.5 KB
    } U;
    __shared__ float s_c0[3], s_c1[3];
    __shared__ double shs[32], shq[32];
    __shared__ float s_a32[32], s_c32[32];
    __shared__ double sh8[8];
    __shared__ float s_a4[4], s_c4[4];

    int tid = threadIdx.x, lane = tid & 31, wid = tid >> 5;
    int gw = blockIdx.x * 8 + wid, nw = gridDim.x * 8;
    int m4 = lane & 3, pl = lane >> 2;
    int pr_i = (lane < 24) ? lane : 23;
    int pair = pr_i / 3, comp = pr_i - pair * 3;

    // ================= phase 0a: qkv (grid-stride over chunks) =================
    {
        for (int e = tid; e < 1024; e += 256) {
            int c = e >> 5, i = e & 31;
            U.q.sW2[0][i * 32 + c] = pack2(Wq[e]);
            U.q.sW2[1][i * 32 + c] = pack2(Wk[e]);
            U.q.sW2[2][i * 32 + c] = pack2(Wv[e]);
        }
        if (tid < 32) { U.q.sb[0][tid] = bq[tid]; U.q.sb[1][tid] = bk[tid]; U.q.sb[2][tid] = bv[tid]; }
        __syncthreads();
        ull bias2[3] = { pack2(U.q.sb[0][lane]), pack2(U.q.sb[1][lane]), pack2(U.q.sb[2][lane]) };
        float* sxf = (float*)&U.q.sx2[wid][0][0];
        for (int chunk = blockIdx.x; chunk < NCHUNK; chunk += gridDim.x) {
            int n0 = chunk * 64 + wid * 8;
#pragma unroll
            for (int pp = 0; pp < 8; pp++) {
                float v = x[(n0 + pp) * 32 + lane];
                sxf[((pp >> 1) * 32 + lane) * 2 + (pp & 1)] = v;
            }
            __syncwarp();
            ull acc[3][4];
#pragma unroll
            for (int m = 0; m < 3; m++)
#pragma unroll
                for (int pr = 0; pr < 4; pr++) acc[m][pr] = bias2[m];
#pragma unroll 4
            for (int i = 0; i < 32; i++) {
                ull w0 = U.q.sW2[0][i * 32 + lane];
                ull w1 = U.q.sW2[1][i * 32 + lane];
                ull w2 = U.q.sW2[2][i * 32 + lane];
#pragma unroll
                for (int pr = 0; pr < 4; pr++) {
                    ull xp = U.q.sx2[wid][pr][i];
                    ffma2(acc[0][pr], w0, xp);
                    ffma2(acc[1][pr], w1, xp);
                    ffma2(acc[2][pr], w2, xp);
                }
            }
#pragma unroll
            for (int pr = 0; pr < 4; pr++) {
                float lo, hi;
                unpack2(acc[0][pr], lo, hi);
                g_q[(n0 + 2 * pr) * 32 + lane] = lo;
                g_q[(n0 + 2 * pr + 1) * 32 + lane] = hi;
                unpack2(acc[1][pr], lo, hi);
                g_k[(n0 + 2 * pr) * 32 + lane] = lo;
                g_k[(n0 + 2 * pr + 1) * 32 + lane] = hi;
                unpack2(acc[2][pr], lo, hi);
                g_v[(n0 + 2 * pr) * 32 + lane] = lo;
                g_v[(n0 + 2 * pr + 1) * 32 + lane] = hi;
            }
            __syncwarp();
        }
    }
    // ================= phase 0b: pstats (grid-stride over pairs) ================
    {
        float W[9], b3[3];
#pragma unroll
        for (int i = 0; i < 9; i++) W[i] = Wp1[i];
#pragma unroll
        for (int i = 0; i < 3; i++) b3[i] = bp1[i];
        float s0 = 0, s1 = 0, s2 = 0, q0 = 0, q1 = 0, q2 = 0;
        for (int pr = blockIdx.x * 256 + tid; pr < NPAIR; pr += G_PERS * 256) {
            int n = pr >> 3;
            int j = __ldg(&idx[pr]);
            float d0 = __ldg(&p[j * 3 + 0]) - __ldg(&p[n * 3 + 0]);
            float d1 = __ldg(&p[j * 3 + 1]) - __ldg(&p[n * 3 + 1]);
            float d2 = __ldg(&p[j * 3 + 2]) - __ldg(&p[n * 3 + 2]);
            float y0 = W[0] * d0 + W[1] * d1 + W[2] * d2 + b3[0];
            float y1 = W[3] * d0 + W[4] * d1 + W[5] * d2 + b3[1];
            float y2 = W[6] * d0 + W[7] * d1 + W[8] * d2 + b3[2];
            s0 += y0; q0 += y0 * y0;
            s1 += y1; q1 += y1 * y1;
            s2 += y2; q2 += y2 * y2;
        }
#pragma unroll
        for (int o = 16; o; o >>= 1) {
            s0 += __shfl_xor_sync(FULLM, s0, o);
            s1 += __shfl_xor_sync(FULLM, s1, o);
            s2 += __shfl_xor_sync(FULLM, s2, o);
            q0 += __shfl_xor_sync(FULLM, q0, o);
            q1 += __shfl_xor_sync(FULLM, q1, o);
            q2 += __shfl_xor_sync(FULLM, q2, o);
        }
        if (tid < 6) shs[tid] = 0.0;
        __syncthreads();
        if (lane == 0) {
            atomicAdd(&shs[0], (double)s0);
            atomicAdd(&shs[1], (double)s1);
            atomicAdd(&shs[2], (double)s2);
            atomicAdd(&shs[3], (double)q0);
            atomicAdd(&shs[4], (double)q1);
            atomicAdd(&shs[5], (double)q2);
        }
        __syncthreads();
        if (tid < 6) atomicAdd(&g_acc[tid], shs[tid]);
    }
    grid_sync(&g_bar[0]);

    float w20 = Wp2[lane * 3 + 0], w21 = Wp2[lane * 3 + 1], w22 = Wp2[lane * 3 + 2];
    float b2 = bp2[lane];

    // ================= phase 1: t3-gen + wstats =================
    {
        if (tid < 3) {
            double M = (double)NPAIR;
            double m = g_acc[tid] / M;
            double var = g_acc[3 + tid] / M - m * m;
            float a = gp[tid] * rsqrtf((float)var + EPSBN);
            s_c0[tid] = a; s_c1[tid] = bpv[tid] - (float)m * a;
        }
        if (tid < 32) { shs[tid] = 0.0; shq[tid] = 0.0; }
        __syncthreads();
        float wc0 = Wp1[comp * 3 + 0], wc1 = Wp1[comp * 3 + 1], wc2 = Wp1[comp * 3 + 2];
        float b3c = bp1[comp];
        float apc = s_c0[comp], cpc = s_c1[comp];
        float s = 0.f, ss = 0.f;
        for (int n = gw; n < QTR_N; n += nw) {
            int jv[4];
            float base[4], t3r[4];
#pragma unroll
            for (int s4 = 0; s4 < 4; s4++) {
                int nn = n + s4 * QTR_N;
                jv[s4] = (lane < 8) ? __ldg(&idx[nn * 8 + lane]) : 0;
                base[s4] = b2 - __ldg(&g_q[nn * 32 + lane]);
            }
            float pd[4];
#pragma unroll
            for (int s4 = 0; s4 < 4; s4++) {
                int nn = n + s4 * QTR_N;
                int jm = __shfl_sync(FULLM, jv[s4], pair);
                pd[s4] = __ldg(&p[jm * 3 + comp]) - __ldg(&p[nn * 3 + comp]);
            }
#pragma unroll
            for (int s4 = 0; s4 < 4; s4++) {
                float d0 = __shfl_sync(FULLM, pd[s4], pair * 3 + 0);
                float d1 = __shfl_sync(FULLM, pd[s4], pair * 3 + 1);
                float d2 = __shfl_sync(FULLM, pd[s4], pair * 3 + 2);
                float y = wc0 * d0 + wc1 * d1 + wc2 * d2 + b3c;
                t3r[s4] = fmaxf(0.f, apc * y + cpc);
            }
            if (lane < 24) {
#pragma unroll
                for (int s4 = 0; s4 < 4; s4++)
                    U.g.st3[wid][s4][pair][comp] = t3r[s4];
            }
            __syncwarp();
#pragma unroll
            for (int ns = 0; ns < 8; ns++)
#pragma unroll
                for (int s4 = 0; s4 < 4; s4++) {
                    int j = __shfl_sync(FULLM, jv[s4], ns);
                    float kv = __ldg(&g_k[j * 32 + lane]);
                    float4 t = *(const float4*)&U.g.st3[wid][s4][ns][0];
                    float prc = w20 * t.x + w21 * t.y + w22 * t.z + base[s4];
                    float wv = kv + prc;
                    s += wv; ss += wv * wv;
                }
            if (lane < 24) {
#pragma unroll
                for (int s4 = 0; s4 < 4; s4++)
                    g_t3[(n + s4 * QTR_N) * 24 + lane] = t3r[s4];
            }
            __syncwarp();
        }
        atomicAdd(&shs[lane], (double)s);
        atomicAdd(&shq[lane], (double)ss);
        __syncthreads();
        if (tid < 32) {
            atomicAdd(&g_acc[6 + tid], shs[tid]);
            atomicAdd(&g_acc[38 + tid], shq[tid]);
        }
    }
    grid_sync(&g_bar[1]);

    // ================= phase 2: t = relu(bn_w(w)) @ Ww1.T + bww1 =================
    {
        if (tid < 32) {
            double M = (double)NPAIR;
            double m = g_acc[6 + tid] / M;
            double var = g_acc[38 + tid] / M - m * m;
            float a = gw1[tid] * rsqrtf((float)var + EPSBN);
            s_a32[tid] = a; s_c32[tid] = bw1[tid] - (float)m * a;
        }
        if (tid < 128) U.g.sWw1[(tid >> 5) * 36 + (tid & 31)] = Ww1[tid];
        if (tid < 8) sh8[tid] = 0.0;
        __syncthreads();
        float aw = s_a32[lane], cw = s_c32[lane];
        float bm = bww1[m4];
        const float4* wr4 = (const float4*)&U.g.sWw1[m4 * 36];
        float sm = 0.f, qm = 0.f;
        for (int n = gw; n < QTR_N; n += nw) {
            int jv[4];
            float base[4];
#pragma unroll
            for (int s4 = 0; s4 < 4; s4++) {
                int nn = n + s4 * QTR_N;
                jv[s4] = (lane < 8) ? __ldg(&idx[nn * 8 + lane]) : 0;
                base[s4] = b2 - __ldg(&g_q[nn * 32 + lane]);
                if (lane < 24)
                    U.g.st3[wid][s4][pair][comp] = __ldg(&g_t3[nn * 24 + lane]);
            }
            __syncwarp();
#pragma unroll
            for (int ns = 0; ns < 8; ns++)
#pragma unroll
                for (int s4 = 0; s4 < 4; s4++) {
                    int j = __shfl_sync(FULLM, jv[s4], ns);
                    float kv = __ldg(&g_k[j * 32 + lane]);
                    float4 t = *(const float4*)&U.g.st3[wid][s4][ns][0];
                    float prc = w20 * t.x + w21 * t.y + w22 * t.z + base[s4];
                    float wv = kv + prc;
                    U.g.sw[wid][s4][ns][lane] = fmaxf(0.f, aw * wv + cw);
                }
            __syncwarp();
            float tv[4] = {bm, bm, bm, bm};
#pragma unroll
            for (int c4 = 0; c4 < 8; c4++) {
                float4 b4 = wr4[c4];
#pragma unroll
                for (int s4 = 0; s4 < 4; s4++) {
                    float4 a4 = ((const float4*)&U.g.sw[wid][s4][pl][0])[c4];
                    tv[s4] += a4.x * b4.x + a4.y * b4.y + a4.z * b4.z + a4.w * b4.w;
                }
            }
#pragma unroll
            for (int s4 = 0; s4 < 4; s4++) {
                g_t[(n + s4 * QTR_N) * 32 + lane] = tv[s4];
                sm += tv[s4]; qm += tv[s4] * tv[s4];
            }
            __syncwarp();
        }
#pragma unroll
        for (int o = 4; o < 32; o <<= 1) {
            sm += __shfl_xor_sync(FULLM, sm, o);
            qm += __shfl_xor_sync(FULLM, qm, o);
        }
        if (lane < 4) {
            atomicAdd(&sh8[lane], (double)sm);
            atomicAdd(&sh8[4 + lane], (double)qm);
        }
        __syncthreads();
        if (tid < 8) atomicAdd(&g_acc[70 + tid], sh8[tid]);
    }
    grid_sync(&g_bar[2]);

    // ================= phase 3: softmax + weighted sum -> out =================
    {
        if (tid < 4) {
            double M = (double)NPAIR;
            double m = g_acc[70 + tid] / M;
            double var = g_acc[74 + tid] / M - m * m;
            float a = gw2[tid] * rsqrtf((float)var + EPSBN);
            s_a4[tid] = a; s_c4[tid] = bw2[tid] - (float)m * a;
        }
        __syncthreads();
        float at0 = s_a4[0], at1 = s_a4[1], at2 = s_a4[2], at3 = s_a4[3];
        float ct0 = s_c4[0], ct1 = s_c4[1], ct2 = s_c4[2], ct3 = s_c4[3];
        float v20 = Ww2[m4 * 4 + 0], v21 = Ww2[m4 * 4 + 1];
        float v22 = Ww2[m4 * 4 + 2], v23 = Ww2[m4 * 4 + 3];
        float bcc = bww2[m4];
        for (int n = gw; n < QTR_N; n += nw) {
            int jv[4];
            float l[4];
#pragma unroll
            for (int s4 = 0; s4 < 4; s4++) {
                int nn = n + s4 * QTR_N;
                jv[s4] = (lane < 8) ? __ldg(&idx[nn * 8 + lane]) : 0;
                if (lane < 24)
                    U.g.st3[wid][s4][pair][comp] = __ldg(&g_t3[nn * 24 + lane]);
                float4 t4 = __ldg((const float4*)&g_t[nn * 32 + pl * 4]);
                float u0 = fmaxf(0.f, at0 * t4.x + ct0);
                float u1 = fmaxf(0.f, at1 * t4.y + ct1);
                float u2 = fmaxf(0.f, at2 * t4.z + ct2);
                float u3 = fmaxf(0.f, at3 * t4.w + ct3);
                l[s4] = v20 * u0 + v21 * u1 + v22 * u2 + v23 * u3 + bcc;
            }
            __syncwarp();
            float mx[4];
#pragma unroll
            for (int s4 = 0; s4 < 4; s4++) mx[s4] = l[s4];
#pragma unroll
            for (int o = 4; o < 32; o <<= 1)
#pragma unroll
                for (int s4 = 0; s4 < 4; s4++)
                    mx[s4] = fmaxf(mx[s4], __shfl_xor_sync(FULLM, mx[s4], o));
            float wn[4], sum[4];
#pragma unroll
            for (int s4 = 0; s4 < 4; s4++) { wn[s4] = __expf(l[s4] - mx[s4]); sum[s4] = wn[s4]; }
#pragma unroll
            for (int o = 4; o < 32; o <<= 1)
#pragma unroll
                for (int s4 = 0; s4 < 4; s4++)
                    sum[s4] += __shfl_xor_sync(FULLM, sum[s4], o);
#pragma unroll
            for (int s4 = 0; s4 < 4; s4++) wn[s4] /= sum[s4];
            float T0[4], T1[4], T2[4];
#pragma unroll
            for (int s4 = 0; s4 < 4; s4++) {
                float4 tm = *(const float4*)&U.g.st3[wid][s4][pl][0];
                T0[s4] = wn[s4] * tm.x;
                T1[s4] = wn[s4] * tm.y;
                T2[s4] = wn[s4] * tm.z;
            }
#pragma unroll
            for (int o = 4; o < 32; o <<= 1)
#pragma unroll
                for (int s4 = 0; s4 < 4; s4++) {
                    T0[s4] += __shfl_xor_sync(FULLM, T0[s4], o);
                    T1[s4] += __shfl_xor_sync(FULLM, T1[s4], o);
                    T2[s4] += __shfl_xor_sync(FULLM, T2[s4], o);
                }
            float o4[4] = {0.f, 0.f, 0.f, 0.f};
#pragma unroll
            for (int ns = 0; ns < 8; ns++)
#pragma unroll
                for (int s4 = 0; s4 < 4; s4++) {
                    int j = __shfl_sync(FULLM, jv[s4], ns);
                    float wg = __shfl_sync(FULLM, wn[s4], ns * 4 + m4);
                    o4[s4] += __ldg(&g_v[j * 32 + lane]) * wg;
                }
#pragma unroll
            for (int s4 = 0; s4 < 4; s4++)
                out[(n + s4 * QTR_N) * 32 + lane] =
                    o4[s4] + w20 * T0[s4] + w21 * T1[s4] + w22 * T2[s4] + b2;
            __syncwarp();
        }
    }
    // last-finishing block resets accumulators + barriers for the next replay
    __syncthreads();
    if (tid == 0) {
        __threadfence();
        unsigned int tk = atomicAdd(&g_ctr, 1u);
        if (tk == gridDim.x - 1) {
            for (int i = 0; i < 78; i++) g_acc[i] = 0.0;
            g_bar[0] = 0u; g_bar[1] = 0u; g_bar[2] = 0u;
            g_ctr = 0u;
        }
    }
}

// ---------------- launch ----------------
extern "C" void kernel_launch(void* const* d_in, const int* in_sizes, int n_in,
                              void* d_out, int out_size) {
    const float* p   = (const float*)d_in[0];
    const float* x   = (const float*)d_in[1];
    const int*   idx = (const int*)d_in[2];
    const float* Wq  = (const float*)d_in[3];  const float* bq   = (const float*)d_in[4];
    const float* Wk  = (const float*)d_in[5];  const float* bk   = (const float*)d_in[6];
    const float* Wv  = (const float*)d_in[7];  const float* bv   = (const float*)d_in[8];
    const float* Wp1 = (const float*)d_in[9];  const float* bp1  = (const float*)d_in[10];
    const float* gp  = (const float*)d_in[11]; const float* bp   = (const float*)d_in[12];
    const float* Wp2 = (const float*)d_in[13]; const float* bp2  = (const float*)d_in[14];
    const float* gw1 = (const float*)d_in[15]; const float* bw1  = (const float*)d_in[16];
    const float* Ww1 = (const float*)d_in[17]; const float* bww1 = (const float*)d_in[18];
    const float* gw2 = (const float*)d_in[19]; const float* bw2  = (const float*)d_in[20];
    const float* Ww2 = (const float*)d_in[21]; const float* bww2 = (const float*)d_in[22];
    float* out = (float*)d_out;

    k_all<<<G_PERS, 256>>>(p, x, idx, Wq, bq, Wk, bk, Wv, bv,
                           gp, bp, Wp1, bp1, Wp2, bp2,
                           gw1, bw1, Ww1, bww1, gw2, bw2, Ww2, bww2, out);
}